// round 16
// baseline (speedup 1.0000x reference)
#include <cuda_runtime.h>
#include <cuda_fp16.h>
#include <cstdint>

#define BB 4
#define NN_SEQ 1024
#define CC 768
#define HH 12
#define HD 64
#define SCALE 0.125f

// Scratch (device globals: allocation-guard safe)
__device__ __half g_q[BB * HH * NN_SEQ * HD];     // pre-scaled by SCALE
__device__ __half g_k[BB * HH * NN_SEQ * HD];
__device__ __half g_v[BB * HH * NN_SEQ * HD];
__device__ __half g_p[(size_t)BB * HH * NN_SEQ * NN_SEQ];  // exp'd premixed, then mixed (in-place)
__device__ float g_lp[BB * HH * NN_SEQ * 16];     // per-ki partial denominators
__device__ float g_sumv[BB * HH * HD];            // column sums of V
__device__ float g_x[BB * NN_SEQ * CC];

// ---------------------------------------------------------------------------
__device__ __forceinline__ unsigned f2tf32(float x) {
    unsigned u;
    asm("cvt.rna.tf32.f32 %0, %1;" : "=r"(u) : "f"(x));
    return u;
}
__device__ __forceinline__ void mma_tf32(float* c, const unsigned* a, const unsigned* b) {
    asm volatile(
        "mma.sync.aligned.m16n8k8.row.col.f32.tf32.tf32.f32 "
        "{%0,%1,%2,%3}, {%4,%5,%6,%7}, {%8,%9}, {%0,%1,%2,%3};\n"
        : "+f"(c[0]), "+f"(c[1]), "+f"(c[2]), "+f"(c[3])
        : "r"(a[0]), "r"(a[1]), "r"(a[2]), "r"(a[3]), "r"(b[0]), "r"(b[1]));
}
__device__ __forceinline__ void mma_f16(float* c, const unsigned* a, const unsigned* b) {
    asm volatile(
        "mma.sync.aligned.m16n8k16.row.col.f32.f16.f16.f32 "
        "{%0,%1,%2,%3}, {%4,%5,%6,%7}, {%8,%9}, {%0,%1,%2,%3};\n"
        : "+f"(c[0]), "+f"(c[1]), "+f"(c[2]), "+f"(c[3])
        : "r"(a[0]), "r"(a[1]), "r"(a[2]), "r"(a[3]), "r"(b[0]), "r"(b[1]));
}
__device__ __forceinline__ unsigned smem_u32(const void* p) {
    return (unsigned)__cvta_generic_to_shared(p);
}
__device__ __forceinline__ void cp_async16(void* dst_smem, const void* src) {
    asm volatile("cp.async.cg.shared.global [%0], [%1], 16;\n"
                 :: "r"(smem_u32(dst_smem)), "l"(src));
}
__device__ __forceinline__ void cp_commit() { asm volatile("cp.async.commit_group;\n"); }
template <int N>
__device__ __forceinline__ void cp_wait_group() {
    asm volatile("cp.async.wait_group %0;\n" :: "n"(N));
}
// Packed f32x2 (FFMA2): two independent f32 FMAs per instruction, same rounding.
__device__ __forceinline__ unsigned long long pk2(float lo, float hi) {
    unsigned long long r;
    asm("mov.b64 %0, {%1, %2};" : "=l"(r) : "f"(lo), "f"(hi));
    return r;
}
__device__ __forceinline__ void upk2(float& lo, float& hi, unsigned long long v) {
    asm("mov.b64 {%0, %1}, %2;" : "=f"(lo), "=f"(hi) : "l"(v));
}
__device__ __forceinline__ void fma2(unsigned long long& d, unsigned long long a, unsigned long long b) {
    asm("fma.rn.f32x2 %0, %1, %2, %3;" : "=l"(d) : "l"(a), "l"(b), "l"(d));
}

// ---------------------------------------------------------------------------
// Kernel 1: QKV GEMM (tf32) -> fp16 q/k/v. Register-prefetched k-tiles.
// ---------------------------------------------------------------------------
__global__ __launch_bounds__(256) void qkv_kernel(const float* __restrict__ X,
                                                  const float* __restrict__ W) {
    __shared__ unsigned As[128][36];
    __shared__ unsigned Bs[32][72];

    const int tid = threadIdx.x, lane = tid & 31, warp = tid >> 5;
    const int wm = warp >> 1, wn = warp & 1;
    const int m0 = blockIdx.y * 128, n0 = blockIdx.x * 64;

    const int ar[4] = {(tid) >> 3, (tid + 256) >> 3, (tid + 512) >> 3, (tid + 768) >> 3};
    const int ac4 = (tid & 7) * 4;
    const int br[2] = {(tid) >> 4, (tid + 256) >> 4};
    const int bc4 = (tid & 15) * 4;

    float acc[2][4][4];
#pragma unroll
    for (int i = 0; i < 2; i++)
#pragma unroll
        for (int j = 0; j < 4; j++)
#pragma unroll
            for (int l = 0; l < 4; l++) acc[i][j][l] = 0.f;

    float4 xa[4], wb[2];
#pragma unroll
    for (int i = 0; i < 4; i++)
        xa[i] = *(const float4*)(X + (size_t)(m0 + ar[i]) * 768 + ac4);
#pragma unroll
    for (int i = 0; i < 2; i++)
        wb[i] = *(const float4*)(W + (size_t)(br[i]) * 2304 + n0 + bc4);

    for (int kt = 0; kt < 768; kt += 32) {
#pragma unroll
        for (int i = 0; i < 4; i++) {
            As[ar[i]][ac4 + 0] = f2tf32(xa[i].x);
            As[ar[i]][ac4 + 1] = f2tf32(xa[i].y);
            As[ar[i]][ac4 + 2] = f2tf32(xa[i].z);
            As[ar[i]][ac4 + 3] = f2tf32(xa[i].w);
        }
#pragma unroll
        for (int i = 0; i < 2; i++) {
            Bs[br[i]][bc4 + 0] = f2tf32(wb[i].x);
            Bs[br[i]][bc4 + 1] = f2tf32(wb[i].y);
            Bs[br[i]][bc4 + 2] = f2tf32(wb[i].z);
            Bs[br[i]][bc4 + 3] = f2tf32(wb[i].w);
        }
        __syncthreads();

        if (kt < 736) {
#pragma unroll
            for (int i = 0; i < 4; i++)
                xa[i] = *(const float4*)(X + (size_t)(m0 + ar[i]) * 768 + kt + 32 + ac4);
#pragma unroll
            for (int i = 0; i < 2; i++)
                wb[i] = *(const float4*)(W + (size_t)(kt + 32 + br[i]) * 2304 + n0 + bc4);
        }

#pragma unroll
        for (int ks = 0; ks < 4; ks++) {
            unsigned a[2][4], b[4][2];
#pragma unroll
            for (int mi = 0; mi < 2; mi++) {
                int r = wm * 32 + mi * 16 + (lane >> 2);
                int c = ks * 8 + (lane & 3);
                a[mi][0] = As[r][c];
                a[mi][1] = As[r + 8][c];
                a[mi][2] = As[r][c + 4];
                a[mi][3] = As[r + 8][c + 4];
            }
#pragma unroll
            for (int ni = 0; ni < 4; ni++) {
                int c = wn * 32 + ni * 8 + (lane >> 2);
                int rk = ks * 8 + (lane & 3);
                b[ni][0] = Bs[rk][c];
                b[ni][1] = Bs[rk + 4][c];
            }
#pragma unroll
            for (int mi = 0; mi < 2; mi++)
#pragma unroll
                for (int ni = 0; ni < 4; ni++) mma_tf32(acc[mi][ni], a[mi], b[ni]);
        }
        __syncthreads();
    }

    const int t = n0 / 768;
    const int hh = (n0 % 768) >> 6;
    __half* dst = (t == 0) ? g_q : (t == 1) ? g_k : g_v;
    const float sc = (t == 0) ? SCALE : 1.0f;

#pragma unroll
    for (int mi = 0; mi < 2; mi++)
#pragma unroll
        for (int ni = 0; ni < 4; ni++) {
            int row = m0 + wm * 32 + mi * 16 + (lane >> 2);
            int col = n0 + wn * 32 + ni * 8 + 2 * (lane & 3);
            int d = col & 63;
            int bb = row >> 10, ns = row & 1023;
            size_t base0 = ((size_t)(bb * HH + hh) * NN_SEQ + ns) * HD;
            size_t base1 = ((size_t)(bb * HH + hh) * NN_SEQ + (ns + 8)) * HD;
            *(__half2*)&dst[base0 + d] = __floats2half2_rn(acc[mi][ni][0] * sc, acc[mi][ni][1] * sc);
            *(__half2*)&dst[base1 + d] = __floats2half2_rn(acc[mi][ni][2] * sc, acc[mi][ni][3] * sc);
        }
}

// ---------------------------------------------------------------------------
// sumv: column sums of V per (b,h).
// ---------------------------------------------------------------------------
__global__ __launch_bounds__(256) void sumv_kernel() {
    __shared__ float red[256];
    const int z = blockIdx.x;
    const int tid = threadIdx.x;
    const int d = tid & 63, kc = tid >> 6;
    float s = 0.f;
    for (int j = 0; j < 256; j++)
        s += __half2float(g_v[((size_t)z * NN_SEQ + kc * 256 + j) * HD + d]);
    red[tid] = s;
    __syncthreads();
    if (tid < 64)
        g_sumv[z * HD + tid] = red[tid] + red[tid + 64] + red[tid + 128] + red[tid + 192];
}

// ---------------------------------------------------------------------------
// attA: R13-proven cp.async double-buffered head loop + FFMA2 premix
// (fma.rn.f32x2: identical f32 arithmetic, half the premix issue slots).
// grid (16 ki, 32 qi, 4 b), 256 threads = 8 warps (warp w = k-strip w*8).
// ---------------------------------------------------------------------------
__global__ __launch_bounds__(256) void attA_kernel(const float* __restrict__ wl) {
    __shared__ __half sQ[2][32 * 72];
    __shared__ __half sK[2][64 * 72];
    __shared__ float sPart[8 * 384];
    __shared__ unsigned long long sWl2[144];   // (w,w) packed pairs

    const int tid = threadIdx.x, lane = tid & 31, w = tid >> 5;
    const int b = blockIdx.z, qi = blockIdx.y, ki = blockIdx.x;
    const int r = lane >> 2, cq = lane & 3;

    const int rr = tid >> 3, c8 = (tid & 7) * 8;
    const int rr1 = (tid + 256) >> 3;
    const size_t hstep = (size_t)NN_SEQ * HD;
    const size_t qoff = ((size_t)(b * HH) * NN_SEQ + qi * 32 + rr) * HD + c8;
    const size_t koff0 = ((size_t)(b * HH) * NN_SEQ + ki * 64 + rr) * HD + c8;
    const size_t koff1 = ((size_t)(b * HH) * NN_SEQ + ki * 64 + rr1) * HD + c8;

    cp_async16(&sQ[0][rr * 72 + c8], g_q + qoff);
    cp_async16(&sK[0][rr * 72 + c8], g_k + koff0);
    cp_async16(&sK[0][rr1 * 72 + c8], g_k + koff1);
    cp_commit();

    if (tid < 144) {
        float wv = wl[tid];
        sWl2[tid] = pk2(wv, wv);
    }

    // accg packed: [g][j] covers elements (mb,e) flattened as j=2*mb+(e>>1)… see unpack
    unsigned long long accg2[12][4];
#pragma unroll
    for (int g = 0; g < 12; g++)
#pragma unroll
        for (int j = 0; j < 4; j++) accg2[g][j] = 0ull;

    for (int h = 0; h < 12; h++) {
        const int buf = h & 1;
        if (h < 11) {
            const int nb = buf ^ 1;
            size_t off = (size_t)(h + 1) * hstep;
            cp_async16(&sQ[nb][rr * 72 + c8], g_q + qoff + off);
            cp_async16(&sK[nb][rr * 72 + c8], g_k + koff0 + off);
            cp_async16(&sK[nb][rr1 * 72 + c8], g_k + koff1 + off);
            cp_commit();
            cp_wait_group<1>();
        } else {
            cp_wait_group<0>();
        }
        __syncthreads();  // head h's data visible; prev reads done (covers sWl2 on h=0)

        float acch[2][4];
#pragma unroll
        for (int mb = 0; mb < 2; mb++)
#pragma unroll
            for (int e = 0; e < 4; e++) acch[mb][e] = 0.f;

#pragma unroll
        for (int dc = 0; dc < 4; dc++) {
            unsigned a[2][4], bf[2];
#pragma unroll
            for (int mb = 0; mb < 2; mb++) {
                const __half* ab = sQ[buf] + (mb * 16 + r) * 72 + dc * 16 + 2 * cq;
                a[mb][0] = *(const unsigned*)(ab);
                a[mb][1] = *(const unsigned*)(ab + 8 * 72);
                a[mb][2] = *(const unsigned*)(ab + 8);
                a[mb][3] = *(const unsigned*)(ab + 8 * 72 + 8);
            }
            const __half* kb = sK[buf] + (w * 8 + r) * 72 + dc * 16 + 2 * cq;
            bf[0] = *(const unsigned*)(kb);
            bf[1] = *(const unsigned*)(kb + 8);
            mma_f16(acch[0], a[0], bf);
            mma_f16(acch[1], a[1], bf);
        }
        // pack acch once per head, premix with FFMA2 (48 fma2 vs 96 fma)
        unsigned long long acch2[4];
        acch2[0] = pk2(acch[0][0], acch[0][1]);
        acch2[1] = pk2(acch[0][2], acch[0][3]);
        acch2[2] = pk2(acch[1][0], acch[1][1]);
        acch2[3] = pk2(acch[1][2], acch[1][3]);
#pragma unroll
        for (int g = 0; g < 12; g++) {
            unsigned long long wg2 = sWl2[h * 12 + g];
            fma2(accg2[g][0], acch2[0], wg2);
            fma2(accg2[g][1], acch2[1], wg2);
            fma2(accg2[g][2], acch2[2], wg2);
            fma2(accg2[g][3], acch2[3], wg2);
        }
        __syncthreads();  // buf consumed; next iter's cp.async may overwrite it
    }

    // exp (clamped) + fp16 store + deterministic per-ki partials
#pragma unroll
    for (int g = 0; g < 12; g++)
#pragma unroll
        for (int mb = 0; mb < 2; mb++) {
            float v0, v1, v2, v3;
            upk2(v0, v1, accg2[g][2 * mb]);
            upk2(v2, v3, accg2[g][2 * mb + 1]);
            float e0 = __expf(fminf(v0, 11.0f));
            float e1 = __expf(fminf(v1, 11.0f));
            float e2 = __expf(fminf(v2, 11.0f));
            float e3 = __expf(fminf(v3, 11.0f));
            int q0 = mb * 16 + r;
            size_t base = ((size_t)((b * HH + g) * NN_SEQ) + qi * 32 + q0) * NN_SEQ + ki * 64 + w * 8 + 2 * cq;
            *(__half2*)(g_p + base)              = __floats2half2_rn(e0, e1);
            *(__half2*)(g_p + base + 8 * NN_SEQ) = __floats2half2_rn(e2, e3);
            float s0 = e0 + e1, s1 = e2 + e3;
            s0 += __shfl_xor_sync(0xffffffffu, s0, 1);
            s0 += __shfl_xor_sync(0xffffffffu, s0, 2);
            s1 += __shfl_xor_sync(0xffffffffu, s1, 1);
            s1 += __shfl_xor_sync(0xffffffffu, s1, 2);
            if (cq == 0) {
                sPart[w * 384 + g * 32 + q0]     = s0;
                sPart[w * 384 + g * 32 + q0 + 8] = s1;
            }
        }
    __syncthreads();
    for (int i = tid; i < 384; i += 256) {
        float s = 0.f;
#pragma unroll
        for (int ww = 0; ww < 8; ww++) s += sPart[ww * 384 + i];
        g_lp[((size_t)(b * HH + (i >> 5)) * NN_SEQ + qi * 32 + (i & 31)) * 16 + ki] = s;
    }
}

// ---------------------------------------------------------------------------
// attB: EXACT R9/R13/R15 version (256 threads, 4 k-pos/thread, uint2 loads).
// grid 4096 (b,q).
// ---------------------------------------------------------------------------
__global__ __launch_bounds__(256) void attB_kernel(const float* __restrict__ ww) {
    __shared__ float sWw[144];
    __shared__ float sIl[12];

    const int tid = threadIdx.x;
    const int b = blockIdx.x >> 10, q = blockIdx.x & 1023;
    if (tid < 144) sWw[tid] = ww[tid];
    if (tid < 12) {
        const float* p = g_lp + ((size_t)(b * HH + tid) * NN_SEQ + q) * 16;
        float s = 0.f;
#pragma unroll
        for (int i = 0; i < 16; i++) s += p[i];
        sIl[tid] = 1.0f / s;
    }
    __syncthreads();

    const int kb = tid * 4;
    float o[12][4];
#pragma unroll
    for (int g2 = 0; g2 < 12; g2++)
#pragma unroll
        for (int e = 0; e < 4; e++) o[g2][e] = 0.f;

#pragma unroll
    for (int g = 0; g < 12; g++) {
        uint2 u = *(const uint2*)(g_p + ((size_t)((b * HH + g) * NN_SEQ) + q) * NN_SEQ + kb);
        const __half2* hp = (const __half2*)&u;
        float2 f0 = __half22float2(hp[0]);
        float2 f1 = __half22float2(hp[1]);
        float il = sIl[g];
        float p0 = f0.x * il, p1 = f0.y * il, p2 = f1.x * il, p3 = f1.y * il;
#pragma unroll
        for (int g2 = 0; g2 < 12; g2++) {
            float wv = sWw[g * 12 + g2];
            o[g2][0] += p0 * wv;
            o[g2][1] += p1 * wv;
            o[g2][2] += p2 * wv;
            o[g2][3] += p3 * wv;
        }
    }
#pragma unroll
    for (int g2 = 0; g2 < 12; g2++) {
        uint2 u;
        __half2* hp = (__half2*)&u;
        hp[0] = __floats2half2_rn(o[g2][0], o[g2][1]);
        hp[1] = __floats2half2_rn(o[g2][2], o[g2][3]);
        *(uint2*)(g_p + ((size_t)((b * HH + g2) * NN_SEQ) + q) * NN_SEQ + kb) = u;
    }
}

// ---------------------------------------------------------------------------
// av: EXACT R9 (proven tiling 128x64, BK=32, fp16 loads -> tf32 MMA).
// grid (8 q, 48 z), 256 threads.
// ---------------------------------------------------------------------------
__global__ __launch_bounds__(256) void av_kernel(const float* __restrict__ bw) {
    __shared__ unsigned As[128][36];
    __shared__ unsigned Bs[32][72];

    const int tid = threadIdx.x, lane = tid & 31, warp = tid >> 5;
    const int wm = warp >> 1, wn = warp & 1;
    const int z = blockIdx.y;
    const int q0 = blockIdx.x * 128;
    const __half* A = g_p + (size_t)z * NN_SEQ * NN_SEQ;
    const __half* V = g_v + (size_t)z * NN_SEQ * HD;

    float acc[2][4][4];
#pragma unroll
    for (int i = 0; i < 2; i++)
#pragma unroll
        for (int j = 0; j < 4; j++)
#pragma unroll
            for (int l = 0; l < 4; l++) acc[i][j][l] = 0.f;

    for (int k0 = 0; k0 < 1024; k0 += 32) {
#pragma unroll
        for (int i = 0; i < 2; i++) {
            int f = tid + i * 256;
            int rr = f >> 2, c8 = (f & 3) * 8;
            uint4 u = *(const uint4*)(A + (size_t)(q0 + rr) * NN_SEQ + k0 + c8);
            const __half2* hp = (const __half2*)&u;
#pragma unroll
            for (int j = 0; j < 4; j++) {
                float2 fv = __half22float2(hp[j]);
                As[rr][c8 + 2 * j]     = __float_as_uint(fv.x);
                As[rr][c8 + 2 * j + 1] = __float_as_uint(fv.y);
            }
        }
        {
            int rr = tid >> 3, c8 = (tid & 7) * 8;
            uint4 u = *(const uint4*)(V + (size_t)(k0 + rr) * HD + c8);
            const __half2* hp = (const __half2*)&u;
#pragma unroll
            for (int j = 0; j < 4; j++) {
                float2 fv = __half22float2(hp[j]);
                Bs[rr][c8 + 2 * j]     = __float_as_uint(fv.x);
                Bs[rr][c8 + 2 * j + 1] = __float_as_uint(fv.y);
            }
        }
        __syncthreads();
#pragma unroll
        for (int ks = 0; ks < 4; ks++) {
            unsigned a[2][4], b[4][2];
#pragma unroll
            for (int mi = 0; mi < 2; mi++) {
                int r = wm * 32 + mi * 16 + (lane >> 2);
                int c = ks * 8 + (lane & 3);
                a[mi][0] = As[r][c];
                a[mi][1] = As[r + 8][c];
                a[mi][2] = As[r][c + 4];
                a[mi][3] = As[r + 8][c + 4];
            }
#pragma unroll
            for (int ni = 0; ni < 4; ni++) {
                int c = wn * 32 + ni * 8 + (lane >> 2);
                int rk = ks * 8 + (lane & 3);
                b[ni][0] = Bs[rk][c];
                b[ni][1] = Bs[rk + 4][c];
            }
#pragma unroll
            for (int mi = 0; mi < 2; mi++)
#pragma unroll
                for (int ni = 0; ni < 4; ni++) mma_tf32(acc[mi][ni], a[mi], b[ni]);
        }
        __syncthreads();
    }

    const int bb = z / HH, g = z % HH;
    const float bwv = bw[g];
#pragma unroll
    for (int mi = 0; mi < 2; mi++)
#pragma unroll
        for (int ni = 0; ni < 4; ni++) {
            int row = q0 + wm * 32 + mi * 16 + (lane >> 2);
            int col = wn * 32 + ni * 8 + 2 * (lane & 3);
            float s0 = g_sumv[z * HD + col];
            float s1 = g_sumv[z * HD + col + 1];
            size_t base0 = ((size_t)(bb * NN_SEQ + row) * CC) + g * HD + col;
            size_t base1 = ((size_t)(bb * NN_SEQ + row + 8) * CC) + g * HD + col;
            g_x[base0]     = acc[mi][ni][0] + bwv * s0;
            g_x[base0 + 1] = acc[mi][ni][1] + bwv * s1;
            g_x[base1]     = acc[mi][ni][2] + bwv * s0;
            g_x[base1 + 1] = acc[mi][ni][3] + bwv * s1;
        }
}

// ---------------------------------------------------------------------------
// proj: out = X @ Wp + bp (tf32). Register-prefetched k-tiles (R14-proven).
// ---------------------------------------------------------------------------
__global__ __launch_bounds__(256) void proj_kernel(const float* __restrict__ Wp,
                                                   const float* __restrict__ bp,
                                                   float* __restrict__ out) {
    __shared__ unsigned As[128][36];
    __shared__ unsigned Bs[32][72];

    const int tid = threadIdx.x, lane = tid & 31, warp = tid >> 5;
    const int wm = warp >> 1, wn = warp & 1;
    const int m0 = blockIdx.y * 128, n0 = blockIdx.x * 64;

    const int ar[4] = {(tid) >> 3, (tid + 256) >> 3, (tid + 512) >> 3, (tid + 768) >> 3};
    const int ac4 = (tid & 7) * 4;
    const int br[2] = {(tid) >> 4, (tid + 256) >> 4};
    const int bc4 = (tid & 15) * 4;

    float acc[2][4][4];
#pragma unroll
    for (int i = 0; i < 2; i++)
#pragma unroll
        for (int j = 0; j < 4; j++)
#pragma unroll
            for (int l = 0; l < 4; l++) acc[i][j][l] = 0.f;

    float4 xa[4], wb[2];
#pragma unroll
    for (int i = 0; i < 4; i++)
        xa[i] = *(const float4*)(g_x + (size_t)(m0 + ar[i]) * 768 + ac4);
#pragma unroll
    for (int i = 0; i < 2; i++)
        wb[i] = *(const float4*)(Wp + (size_t)(br[i]) * 768 + n0 + bc4);

    for (int kt = 0; kt < 768; kt += 32) {
#pragma unroll
        for (int i = 0; i < 4; i++) {
            As[ar[i]][ac4 + 0] = f2tf32(xa[i].x);
            As[ar[i]][ac4 + 1] = f2tf32(xa[i].y);
            As[ar[i]][ac4 + 2] = f2tf32(xa[i].z);
            As[ar[i]][ac4 + 3] = f2tf32(xa[i].w);
        }
#pragma unroll
        for (int i = 0; i < 2; i++) {
            Bs[br[i]][bc4 + 0] = f2tf32(wb[i].x);
            Bs[br[i]][bc4 + 1] = f2tf32(wb[i].y);
            Bs[br[i]][bc4 + 2] = f2tf32(wb[i].z);
            Bs[br[i]][bc4 + 3] = f2tf32(wb[i].w);
        }
        __syncthreads();

        if (kt < 736) {
#pragma unroll
            for (int i = 0; i < 4; i++)
                xa[i] = *(const float4*)(g_x + (size_t)(m0 + ar[i]) * 768 + kt + 32 + ac4);
#pragma unroll
            for (int i = 0; i < 2; i++)
                wb[i] = *(const float4*)(Wp + (size_t)(kt + 32 + br[i]) * 768 + n0 + bc4);
        }

#pragma unroll
        for (int ks = 0; ks < 4; ks++) {
            unsigned a[2][4], b[4][2];
#pragma unroll
            for (int mi = 0; mi < 2; mi++) {
                int r = wm * 32 + mi * 16 + (lane >> 2);
                int c = ks * 8 + (lane & 3);
                a[mi][0] = As[r][c];
                a[mi][1] = As[r + 8][c];
                a[mi][2] = As[r][c + 4];
                a[mi][3] = As[r + 8][c + 4];
            }
#pragma unroll
            for (int ni = 0; ni < 4; ni++) {
                int c = wn * 32 + ni * 8 + (lane >> 2);
                int rk = ks * 8 + (lane & 3);
                b[ni][0] = Bs[rk][c];
                b[ni][1] = Bs[rk + 4][c];
            }
#pragma unroll
            for (int mi = 0; mi < 2; mi++)
#pragma unroll
                for (int ni = 0; ni < 4; ni++) mma_tf32(acc[mi][ni], a[mi], b[ni]);
        }
        __syncthreads();
    }

#pragma unroll
    for (int mi = 0; mi < 2; mi++)
#pragma unroll
        for (int ni = 0; ni < 4; ni++) {
            int row = m0 + wm * 32 + mi * 16 + (lane >> 2);
            int col = n0 + wn * 32 + ni * 8 + 2 * (lane & 3);
            float b0 = __ldg(&bp[col]), b1 = __ldg(&bp[col + 1]);
            out[(size_t)row * 768 + col]       = acc[mi][ni][0] + b0;
            out[(size_t)row * 768 + col + 1]   = acc[mi][ni][1] + b1;
            out[(size_t)(row + 8) * 768 + col]     = acc[mi][ni][2] + b0;
            out[(size_t)(row + 8) * 768 + col + 1] = acc[mi][ni][3] + b1;
        }
}

// ---------------------------------------------------------------------------
extern "C" void kernel_launch(void* const* d_in, const int* in_sizes, int n_in,
                              void* d_out, int out_size) {
    const float* X    = (const float*)d_in[0];
    const float* Wqkv = (const float*)d_in[1];
    const float* Wl   = (const float*)d_in[2];
    const float* Bl   = (const float*)d_in[3];  // constant over softmax axis -> cancels exactly
    const float* Ww   = (const float*)d_in[4];
    const float* Bw   = (const float*)d_in[5];
    const float* Wp   = (const float*)d_in[6];
    const float* Bp   = (const float*)d_in[7];
    float* out = (float*)d_out;
    (void)Bl;

    qkv_kernel<<<dim3(36, 32), 256>>>(X, Wqkv);
    sumv_kernel<<<48, 256>>>();
    attA_kernel<<<dim3(16, 32, 4), 256>>>(Wl);
    attB_kernel<<<4096, 256>>>(Ww);
    av_kernel<<<dim3(8, 48), 256>>>(Bw);
    proj_kernel<<<dim3(12, 32), 256>>>(Wp, Bp, out);
}

// round 17
// speedup vs baseline: 1.0452x; 1.0452x over previous
#include <cuda_runtime.h>
#include <cuda_fp16.h>
#include <cstdint>

#define BB 4
#define NN_SEQ 1024
#define CC 768
#define HH 12
#define HD 64
#define SCALE 0.125f

// Scratch (device globals: allocation-guard safe)
__device__ __half g_q[BB * HH * NN_SEQ * HD];     // pre-scaled by SCALE
__device__ __half g_k[BB * HH * NN_SEQ * HD];
__device__ __half g_v[BB * HH * NN_SEQ * HD];
__device__ __half g_p[(size_t)BB * HH * NN_SEQ * NN_SEQ];  // exp'd premixed, then mixed (in-place)
__device__ float g_lp[BB * HH * NN_SEQ * 16];     // per-ki partial denominators
__device__ float g_sumv[BB * HH * HD];            // column sums of V
__device__ float g_x[BB * NN_SEQ * CC];

// ---------------------------------------------------------------------------
__device__ __forceinline__ unsigned f2tf32(float x) {
    unsigned u;
    asm("cvt.rna.tf32.f32 %0, %1;" : "=r"(u) : "f"(x));
    return u;
}
__device__ __forceinline__ void mma_tf32(float* c, const unsigned* a, const unsigned* b) {
    asm volatile(
        "mma.sync.aligned.m16n8k8.row.col.f32.tf32.tf32.f32 "
        "{%0,%1,%2,%3}, {%4,%5,%6,%7}, {%8,%9}, {%0,%1,%2,%3};\n"
        : "+f"(c[0]), "+f"(c[1]), "+f"(c[2]), "+f"(c[3])
        : "r"(a[0]), "r"(a[1]), "r"(a[2]), "r"(a[3]), "r"(b[0]), "r"(b[1]));
}
__device__ __forceinline__ void mma_f16(float* c, const unsigned* a, const unsigned* b) {
    asm volatile(
        "mma.sync.aligned.m16n8k16.row.col.f32.f16.f16.f32 "
        "{%0,%1,%2,%3}, {%4,%5,%6,%7}, {%8,%9}, {%0,%1,%2,%3};\n"
        : "+f"(c[0]), "+f"(c[1]), "+f"(c[2]), "+f"(c[3])
        : "r"(a[0]), "r"(a[1]), "r"(a[2]), "r"(a[3]), "r"(b[0]), "r"(b[1]));
}
__device__ __forceinline__ unsigned smem_u32(const void* p) {
    return (unsigned)__cvta_generic_to_shared(p);
}
__device__ __forceinline__ void cp_async16(void* dst_smem, const void* src) {
    asm volatile("cp.async.cg.shared.global [%0], [%1], 16;\n"
                 :: "r"(smem_u32(dst_smem)), "l"(src));
}
__device__ __forceinline__ void cp_commit() { asm volatile("cp.async.commit_group;\n"); }
template <int N>
__device__ __forceinline__ void cp_wait_group() {
    asm volatile("cp.async.wait_group %0;\n" :: "n"(N));
}

// ---------------------------------------------------------------------------
// Kernel 1: QKV GEMM (tf32) -> fp16 q/k/v. Register-prefetched k-tiles.
// ---------------------------------------------------------------------------
__global__ __launch_bounds__(256) void qkv_kernel(const float* __restrict__ X,
                                                  const float* __restrict__ W) {
    __shared__ unsigned As[128][36];
    __shared__ unsigned Bs[32][72];

    const int tid = threadIdx.x, lane = tid & 31, warp = tid >> 5;
    const int wm = warp >> 1, wn = warp & 1;
    const int m0 = blockIdx.y * 128, n0 = blockIdx.x * 64;

    const int ar[4] = {(tid) >> 3, (tid + 256) >> 3, (tid + 512) >> 3, (tid + 768) >> 3};
    const int ac4 = (tid & 7) * 4;
    const int br[2] = {(tid) >> 4, (tid + 256) >> 4};
    const int bc4 = (tid & 15) * 4;

    float acc[2][4][4];
#pragma unroll
    for (int i = 0; i < 2; i++)
#pragma unroll
        for (int j = 0; j < 4; j++)
#pragma unroll
            for (int l = 0; l < 4; l++) acc[i][j][l] = 0.f;

    float4 xa[4], wb[2];
#pragma unroll
    for (int i = 0; i < 4; i++)
        xa[i] = *(const float4*)(X + (size_t)(m0 + ar[i]) * 768 + ac4);
#pragma unroll
    for (int i = 0; i < 2; i++)
        wb[i] = *(const float4*)(W + (size_t)(br[i]) * 2304 + n0 + bc4);

    for (int kt = 0; kt < 768; kt += 32) {
#pragma unroll
        for (int i = 0; i < 4; i++) {
            As[ar[i]][ac4 + 0] = f2tf32(xa[i].x);
            As[ar[i]][ac4 + 1] = f2tf32(xa[i].y);
            As[ar[i]][ac4 + 2] = f2tf32(xa[i].z);
            As[ar[i]][ac4 + 3] = f2tf32(xa[i].w);
        }
#pragma unroll
        for (int i = 0; i < 2; i++) {
            Bs[br[i]][bc4 + 0] = f2tf32(wb[i].x);
            Bs[br[i]][bc4 + 1] = f2tf32(wb[i].y);
            Bs[br[i]][bc4 + 2] = f2tf32(wb[i].z);
            Bs[br[i]][bc4 + 3] = f2tf32(wb[i].w);
        }
        __syncthreads();

        if (kt < 736) {
#pragma unroll
            for (int i = 0; i < 4; i++)
                xa[i] = *(const float4*)(X + (size_t)(m0 + ar[i]) * 768 + kt + 32 + ac4);
#pragma unroll
            for (int i = 0; i < 2; i++)
                wb[i] = *(const float4*)(W + (size_t)(kt + 32 + br[i]) * 2304 + n0 + bc4);
        }

#pragma unroll
        for (int ks = 0; ks < 4; ks++) {
            unsigned a[2][4], b[4][2];
#pragma unroll
            for (int mi = 0; mi < 2; mi++) {
                int r = wm * 32 + mi * 16 + (lane >> 2);
                int c = ks * 8 + (lane & 3);
                a[mi][0] = As[r][c];
                a[mi][1] = As[r + 8][c];
                a[mi][2] = As[r][c + 4];
                a[mi][3] = As[r + 8][c + 4];
            }
#pragma unroll
            for (int ni = 0; ni < 4; ni++) {
                int c = wn * 32 + ni * 8 + (lane >> 2);
                int rk = ks * 8 + (lane & 3);
                b[ni][0] = Bs[rk][c];
                b[ni][1] = Bs[rk + 4][c];
            }
#pragma unroll
            for (int mi = 0; mi < 2; mi++)
#pragma unroll
                for (int ni = 0; ni < 4; ni++) mma_tf32(acc[mi][ni], a[mi], b[ni]);
        }
        __syncthreads();
    }

    const int t = n0 / 768;
    const int hh = (n0 % 768) >> 6;
    __half* dst = (t == 0) ? g_q : (t == 1) ? g_k : g_v;
    const float sc = (t == 0) ? SCALE : 1.0f;

#pragma unroll
    for (int mi = 0; mi < 2; mi++)
#pragma unroll
        for (int ni = 0; ni < 4; ni++) {
            int row = m0 + wm * 32 + mi * 16 + (lane >> 2);
            int col = n0 + wn * 32 + ni * 8 + 2 * (lane & 3);
            int d = col & 63;
            int bb = row >> 10, ns = row & 1023;
            size_t base0 = ((size_t)(bb * HH + hh) * NN_SEQ + ns) * HD;
            size_t base1 = ((size_t)(bb * HH + hh) * NN_SEQ + (ns + 8)) * HD;
            *(__half2*)&dst[base0 + d] = __floats2half2_rn(acc[mi][ni][0] * sc, acc[mi][ni][1] * sc);
            *(__half2*)&dst[base1 + d] = __floats2half2_rn(acc[mi][ni][2] * sc, acc[mi][ni][3] * sc);
        }
}

// ---------------------------------------------------------------------------
// sumv: column sums of V per (b,h).
// ---------------------------------------------------------------------------
__global__ __launch_bounds__(256) void sumv_kernel() {
    __shared__ float red[256];
    const int z = blockIdx.x;
    const int tid = threadIdx.x;
    const int d = tid & 63, kc = tid >> 6;
    float s = 0.f;
    for (int j = 0; j < 256; j++)
        s += __half2float(g_v[((size_t)z * NN_SEQ + kc * 256 + j) * HD + d]);
    red[tid] = s;
    __syncthreads();
    if (tid < 64)
        g_sumv[z * HD + tid] = red[tid] + red[tid + 64] + red[tid + 128] + red[tid + 192];
}

// ---------------------------------------------------------------------------
// attA: R13/R15-proven mainloop (cp.async dbuf, fp16 MMA, scalar f32 premix)
// + NEW smem-staged COALESCED p writeout (was: scattered 4B stores at ~50%
// sector efficiency; now: 128B/warp uint4 stores via dead sQ[0] buffer).
// grid (16 ki, 32 qi, 4 b), 256 threads = 8 warps (warp w = k-strip w*8).
// ---------------------------------------------------------------------------
__global__ __launch_bounds__(256) void attA_kernel(const float* __restrict__ wl) {
    __shared__ __half sQ[2][32 * 72];
    __shared__ __half sK[2][64 * 72];
    __shared__ float sPart[8 * 384];
    __shared__ float sWl[144];

    const int tid = threadIdx.x, lane = tid & 31, w = tid >> 5;
    const int b = blockIdx.z, qi = blockIdx.y, ki = blockIdx.x;
    const int r = lane >> 2, cq = lane & 3;

    const int rr = tid >> 3, c8 = (tid & 7) * 8;
    const int rr1 = (tid + 256) >> 3;
    const size_t hstep = (size_t)NN_SEQ * HD;
    const size_t qoff = ((size_t)(b * HH) * NN_SEQ + qi * 32 + rr) * HD + c8;
    const size_t koff0 = ((size_t)(b * HH) * NN_SEQ + ki * 64 + rr) * HD + c8;
    const size_t koff1 = ((size_t)(b * HH) * NN_SEQ + ki * 64 + rr1) * HD + c8;

    cp_async16(&sQ[0][rr * 72 + c8], g_q + qoff);
    cp_async16(&sK[0][rr * 72 + c8], g_k + koff0);
    cp_async16(&sK[0][rr1 * 72 + c8], g_k + koff1);
    cp_commit();

    if (tid < 144) sWl[tid] = wl[tid];

    float accg[12][2][4];
#pragma unroll
    for (int g = 0; g < 12; g++)
#pragma unroll
        for (int mb = 0; mb < 2; mb++)
#pragma unroll
            for (int e = 0; e < 4; e++) accg[g][mb][e] = 0.f;

    for (int h = 0; h < 12; h++) {
        const int buf = h & 1;
        if (h < 11) {
            const int nb = buf ^ 1;
            size_t off = (size_t)(h + 1) * hstep;
            cp_async16(&sQ[nb][rr * 72 + c8], g_q + qoff + off);
            cp_async16(&sK[nb][rr * 72 + c8], g_k + koff0 + off);
            cp_async16(&sK[nb][rr1 * 72 + c8], g_k + koff1 + off);
            cp_commit();
            cp_wait_group<1>();
        } else {
            cp_wait_group<0>();
        }
        __syncthreads();

        float acch[2][4];
#pragma unroll
        for (int mb = 0; mb < 2; mb++)
#pragma unroll
            for (int e = 0; e < 4; e++) acch[mb][e] = 0.f;

#pragma unroll
        for (int dc = 0; dc < 4; dc++) {
            unsigned a[2][4], bf[2];
#pragma unroll
            for (int mb = 0; mb < 2; mb++) {
                const __half* ab = sQ[buf] + (mb * 16 + r) * 72 + dc * 16 + 2 * cq;
                a[mb][0] = *(const unsigned*)(ab);
                a[mb][1] = *(const unsigned*)(ab + 8 * 72);
                a[mb][2] = *(const unsigned*)(ab + 8);
                a[mb][3] = *(const unsigned*)(ab + 8 * 72 + 8);
            }
            const __half* kb = sK[buf] + (w * 8 + r) * 72 + dc * 16 + 2 * cq;
            bf[0] = *(const unsigned*)(kb);
            bf[1] = *(const unsigned*)(kb + 8);
            mma_f16(acch[0], a[0], bf);
            mma_f16(acch[1], a[1], bf);
        }
#pragma unroll
        for (int g = 0; g < 12; g++) {
            float wg = sWl[h * 12 + g];
#pragma unroll
            for (int mb = 0; mb < 2; mb++)
#pragma unroll
                for (int e = 0; e < 4; e++) accg[g][mb][e] += acch[mb][e] * wg;
        }
        __syncthreads();  // buf consumed; next iter's cp.async may overwrite it
    }

    // Epilogue: per head, exp + stage fp16 tile in dead sQ[0] -> coalesced store.
    __half* sStage = &sQ[0][0];  // 32x72 halves; Q/K buffers dead after the loop
#pragma unroll
    for (int g = 0; g < 12; g++) {
#pragma unroll
        for (int mb = 0; mb < 2; mb++) {
            float e0 = __expf(fminf(accg[g][mb][0], 11.0f));
            float e1 = __expf(fminf(accg[g][mb][1], 11.0f));
            float e2 = __expf(fminf(accg[g][mb][2], 11.0f));
            float e3 = __expf(fminf(accg[g][mb][3], 11.0f));
            int q0 = mb * 16 + r;
            *(__half2*)(sStage + q0 * 72 + w * 8 + 2 * cq)       = __floats2half2_rn(e0, e1);
            *(__half2*)(sStage + (q0 + 8) * 72 + w * 8 + 2 * cq) = __floats2half2_rn(e2, e3);
            float s0 = e0 + e1, s1 = e2 + e3;
            s0 += __shfl_xor_sync(0xffffffffu, s0, 1);
            s0 += __shfl_xor_sync(0xffffffffu, s0, 2);
            s1 += __shfl_xor_sync(0xffffffffu, s1, 1);
            s1 += __shfl_xor_sync(0xffffffffu, s1, 2);
            if (cq == 0) {
                sPart[w * 384 + g * 32 + q0]     = s0;
                sPart[w * 384 + g * 32 + q0 + 8] = s1;
            }
        }
        __syncthreads();  // stage complete
        // coalesced store: 256 uint4 = 32 rows x 128B, 128B per warp-quarter row
        *(uint4*)(g_p + ((size_t)((b * HH + g) * NN_SEQ) + qi * 32 + rr) * NN_SEQ + ki * 64 + c8) =
            *(const uint4*)(sStage + rr * 72 + c8);
        __syncthreads();  // stage reusable for next g
    }

    for (int i = tid; i < 384; i += 256) {
        float s = 0.f;
#pragma unroll
        for (int ww = 0; ww < 8; ww++) s += sPart[ww * 384 + i];
        g_lp[((size_t)(b * HH + (i >> 5)) * NN_SEQ + qi * 32 + (i & 31)) * 16 + ki] = s;
    }
}

// ---------------------------------------------------------------------------
// attB: EXACT R9/R13/R15 version (256 threads, 4 k-pos/thread, uint2 loads).
// grid 4096 (b,q).
// ---------------------------------------------------------------------------
__global__ __launch_bounds__(256) void attB_kernel(const float* __restrict__ ww) {
    __shared__ float sWw[144];
    __shared__ float sIl[12];

    const int tid = threadIdx.x;
    const int b = blockIdx.x >> 10, q = blockIdx.x & 1023;
    if (tid < 144) sWw[tid] = ww[tid];
    if (tid < 12) {
        const float* p = g_lp + ((size_t)(b * HH + tid) * NN_SEQ + q) * 16;
        float s = 0.f;
#pragma unroll
        for (int i = 0; i < 16; i++) s += p[i];
        sIl[tid] = 1.0f / s;
    }
    __syncthreads();

    const int kb = tid * 4;
    float o[12][4];
#pragma unroll
    for (int g2 = 0; g2 < 12; g2++)
#pragma unroll
        for (int e = 0; e < 4; e++) o[g2][e] = 0.f;

#pragma unroll
    for (int g = 0; g < 12; g++) {
        uint2 u = *(const uint2*)(g_p + ((size_t)((b * HH + g) * NN_SEQ) + q) * NN_SEQ + kb);
        const __half2* hp = (const __half2*)&u;
        float2 f0 = __half22float2(hp[0]);
        float2 f1 = __half22float2(hp[1]);
        float il = sIl[g];
        float p0 = f0.x * il, p1 = f0.y * il, p2 = f1.x * il, p3 = f1.y * il;
#pragma unroll
        for (int g2 = 0; g2 < 12; g2++) {
            float wv = sWw[g * 12 + g2];
            o[g2][0] += p0 * wv;
            o[g2][1] += p1 * wv;
            o[g2][2] += p2 * wv;
            o[g2][3] += p3 * wv;
        }
    }
#pragma unroll
    for (int g2 = 0; g2 < 12; g2++) {
        uint2 u;
        __half2* hp = (__half2*)&u;
        hp[0] = __floats2half2_rn(o[g2][0], o[g2][1]);
        hp[1] = __floats2half2_rn(o[g2][2], o[g2][3]);
        *(uint2*)(g_p + ((size_t)((b * HH + g2) * NN_SEQ) + q) * NN_SEQ + kb) = u;
    }
}

// ---------------------------------------------------------------------------
// av: EXACT R9 (proven tiling 128x64, BK=32, fp16 loads -> tf32 MMA).
// grid (8 q, 48 z), 256 threads.
// ---------------------------------------------------------------------------
__global__ __launch_bounds__(256) void av_kernel(const float* __restrict__ bw) {
    __shared__ unsigned As[128][36];
    __shared__ unsigned Bs[32][72];

    const int tid = threadIdx.x, lane = tid & 31, warp = tid >> 5;
    const int wm = warp >> 1, wn = warp & 1;
    const int z = blockIdx.y;
    const int q0 = blockIdx.x * 128;
    const __half* A = g_p + (size_t)z * NN_SEQ * NN_SEQ;
    const __half* V = g_v + (size_t)z * NN_SEQ * HD;

    float acc[2][4][4];
#pragma unroll
    for (int i = 0; i < 2; i++)
#pragma unroll
        for (int j = 0; j < 4; j++)
#pragma unroll
            for (int l = 0; l < 4; l++) acc[i][j][l] = 0.f;

    for (int k0 = 0; k0 < 1024; k0 += 32) {
#pragma unroll
        for (int i = 0; i < 2; i++) {
            int f = tid + i * 256;
            int rr = f >> 2, c8 = (f & 3) * 8;
            uint4 u = *(const uint4*)(A + (size_t)(q0 + rr) * NN_SEQ + k0 + c8);
            const __half2* hp = (const __half2*)&u;
#pragma unroll
            for (int j = 0; j < 4; j++) {
                float2 fv = __half22float2(hp[j]);
                As[rr][c8 + 2 * j]     = __float_as_uint(fv.x);
                As[rr][c8 + 2 * j + 1] = __float_as_uint(fv.y);
            }
        }
        {
            int rr = tid >> 3, c8 = (tid & 7) * 8;
            uint4 u = *(const uint4*)(V + (size_t)(k0 + rr) * HD + c8);
            const __half2* hp = (const __half2*)&u;
#pragma unroll
            for (int j = 0; j < 4; j++) {
                float2 fv = __half22float2(hp[j]);
                Bs[rr][c8 + 2 * j]     = __float_as_uint(fv.x);
                Bs[rr][c8 + 2 * j + 1] = __float_as_uint(fv.y);
            }
        }
        __syncthreads();
#pragma unroll
        for (int ks = 0; ks < 4; ks++) {
            unsigned a[2][4], b[4][2];
#pragma unroll
            for (int mi = 0; mi < 2; mi++) {
                int r = wm * 32 + mi * 16 + (lane >> 2);
                int c = ks * 8 + (lane & 3);
                a[mi][0] = As[r][c];
                a[mi][1] = As[r + 8][c];
                a[mi][2] = As[r][c + 4];
                a[mi][3] = As[r + 8][c + 4];
            }
#pragma unroll
            for (int ni = 0; ni < 4; ni++) {
                int c = wn * 32 + ni * 8 + (lane >> 2);
                int rk = ks * 8 + (lane & 3);
                b[ni][0] = Bs[rk][c];
                b[ni][1] = Bs[rk + 4][c];
            }
#pragma unroll
            for (int mi = 0; mi < 2; mi++)
#pragma unroll
                for (int ni = 0; ni < 4; ni++) mma_tf32(acc[mi][ni], a[mi], b[ni]);
        }
        __syncthreads();
    }

    const int bb = z / HH, g = z % HH;
    const float bwv = bw[g];
#pragma unroll
    for (int mi = 0; mi < 2; mi++)
#pragma unroll
        for (int ni = 0; ni < 4; ni++) {
            int row = q0 + wm * 32 + mi * 16 + (lane >> 2);
            int col = wn * 32 + ni * 8 + 2 * (lane & 3);
            float s0 = g_sumv[z * HD + col];
            float s1 = g_sumv[z * HD + col + 1];
            size_t base0 = ((size_t)(bb * NN_SEQ + row) * CC) + g * HD + col;
            size_t base1 = ((size_t)(bb * NN_SEQ + row + 8) * CC) + g * HD + col;
            g_x[base0]     = acc[mi][ni][0] + bwv * s0;
            g_x[base0 + 1] = acc[mi][ni][1] + bwv * s1;
            g_x[base1]     = acc[mi][ni][2] + bwv * s0;
            g_x[base1 + 1] = acc[mi][ni][3] + bwv * s1;
        }
}

// ---------------------------------------------------------------------------
// proj: out = X @ Wp + bp (tf32). Register-prefetched k-tiles (R14-proven).
// ---------------------------------------------------------------------------
__global__ __launch_bounds__(256) void proj_kernel(const float* __restrict__ Wp,
                                                   const float* __restrict__ bp,
                                                   float* __restrict__ out) {
    __shared__ unsigned As[128][36];
    __shared__ unsigned Bs[32][72];

    const int tid = threadIdx.x, lane = tid & 31, warp = tid >> 5;
    const int wm = warp >> 1, wn = warp & 1;
    const int m0 = blockIdx.y * 128, n0 = blockIdx.x * 64;

    const int ar[4] = {(tid) >> 3, (tid + 256) >> 3, (tid + 512) >> 3, (tid + 768) >> 3};
    const int ac4 = (tid & 7) * 4;
    const int br[2] = {(tid) >> 4, (tid + 256) >> 4};
    const int bc4 = (tid & 15) * 4;

    float acc[2][4][4];
#pragma unroll
    for (int i = 0; i < 2; i++)
#pragma unroll
        for (int j = 0; j < 4; j++)
#pragma unroll
            for (int l = 0; l < 4; l++) acc[i][j][l] = 0.f;

    float4 xa[4], wb[2];
#pragma unroll
    for (int i = 0; i < 4; i++)
        xa[i] = *(const float4*)(g_x + (size_t)(m0 + ar[i]) * 768 + ac4);
#pragma unroll
    for (int i = 0; i < 2; i++)
        wb[i] = *(const float4*)(Wp + (size_t)(br[i]) * 768 + n0 + bc4);

    for (int kt = 0; kt < 768; kt += 32) {
#pragma unroll
        for (int i = 0; i < 4; i++) {
            As[ar[i]][ac4 + 0] = f2tf32(xa[i].x);
            As[ar[i]][ac4 + 1] = f2tf32(xa[i].y);
            As[ar[i]][ac4 + 2] = f2tf32(xa[i].z);
            As[ar[i]][ac4 + 3] = f2tf32(xa[i].w);
        }
#pragma unroll
        for (int i = 0; i < 2; i++) {
            Bs[br[i]][bc4 + 0] = f2tf32(wb[i].x);
            Bs[br[i]][bc4 + 1] = f2tf32(wb[i].y);
            Bs[br[i]][bc4 + 2] = f2tf32(wb[i].z);
            Bs[br[i]][bc4 + 3] = f2tf32(wb[i].w);
        }
        __syncthreads();

        if (kt < 736) {
#pragma unroll
            for (int i = 0; i < 4; i++)
                xa[i] = *(const float4*)(g_x + (size_t)(m0 + ar[i]) * 768 + kt + 32 + ac4);
#pragma unroll
            for (int i = 0; i < 2; i++)
                wb[i] = *(const float4*)(Wp + (size_t)(kt + 32 + br[i]) * 768 + n0 + bc4);
        }

#pragma unroll
        for (int ks = 0; ks < 4; ks++) {
            unsigned a[2][4], b[4][2];
#pragma unroll
            for (int mi = 0; mi < 2; mi++) {
                int r = wm * 32 + mi * 16 + (lane >> 2);
                int c = ks * 8 + (lane & 3);
                a[mi][0] = As[r][c];
                a[mi][1] = As[r + 8][c];
                a[mi][2] = As[r][c + 4];
                a[mi][3] = As[r + 8][c + 4];
            }
#pragma unroll
            for (int ni = 0; ni < 4; ni++) {
                int c = wn * 32 + ni * 8 + (lane >> 2);
                int rk = ks * 8 + (lane & 3);
                b[ni][0] = Bs[rk][c];
                b[ni][1] = Bs[rk + 4][c];
            }
#pragma unroll
            for (int mi = 0; mi < 2; mi++)
#pragma unroll
                for (int ni = 0; ni < 4; ni++) mma_tf32(acc[mi][ni], a[mi], b[ni]);
        }
        __syncthreads();
    }

#pragma unroll
    for (int mi = 0; mi < 2; mi++)
#pragma unroll
        for (int ni = 0; ni < 4; ni++) {
            int row = m0 + wm * 32 + mi * 16 + (lane >> 2);
            int col = n0 + wn * 32 + ni * 8 + 2 * (lane & 3);
            float b0 = __ldg(&bp[col]), b1 = __ldg(&bp[col + 1]);
            out[(size_t)row * 768 + col]       = acc[mi][ni][0] + b0;
            out[(size_t)row * 768 + col + 1]   = acc[mi][ni][1] + b1;
            out[(size_t)(row + 8) * 768 + col]     = acc[mi][ni][2] + b0;
            out[(size_t)(row + 8) * 768 + col + 1] = acc[mi][ni][3] + b1;
        }
}

// ---------------------------------------------------------------------------
extern "C" void kernel_launch(void* const* d_in, const int* in_sizes, int n_in,
                              void* d_out, int out_size) {
    const float* X    = (const float*)d_in[0];
    const float* Wqkv = (const float*)d_in[1];
    const float* Wl   = (const float*)d_in[2];
    const float* Bl   = (const float*)d_in[3];  // constant over softmax axis -> cancels exactly
    const float* Ww   = (const float*)d_in[4];
    const float* Bw   = (const float*)d_in[5];
    const float* Wp   = (const float*)d_in[6];
    const float* Bp   = (const float*)d_in[7];
    float* out = (float*)d_out;
    (void)Bl;

    qkv_kernel<<<dim3(36, 32), 256>>>(X, Wqkv);
    sumv_kernel<<<48, 256>>>();
    attA_kernel<<<dim3(16, 32, 4), 256>>>(Wl);
    attB_kernel<<<4096, 256>>>(Ww);
    av_kernel<<<dim3(8, 48), 256>>>(Bw);
    proj_kernel<<<dim3(12, 32), 256>>>(Wp, Bp, out);
}